// round 2
// baseline (speedup 1.0000x reference)
#include <cuda_runtime.h>
#include <math.h>

#define NBATCH 64
#define NANC   3
#define NCLS   13
#define NHH    76
#define NWW    76
#define NPIX   (NHH*NWW)          // 5776
#define NANCH  (NANC*NPIX)        // 17328
#define CADT   (NBATCH*NANCH)     // 1108992
#define MAXT   50
#define NLV    12                 // NL
#define NCH    (NLV+NCLS)         // 25 channels per anchor
#define BETA_C 0.028f
#define EPSF   1e-12f
#define NETWH  608.0f
#define IGN    0.5f

// -------- scratch (device globals; no allocation) --------
__device__ int      g_recidx[CADT];            // -1 or record index (winner)
__device__ float    g_rec[NBATCH*MAXT][12];    // vals[0..10], iou_t at [11]
__device__ unsigned g_clsmask[NBATCH*MAXT];    // OR of class one-hots at that cell
__device__ float4   g_gtb[NBATCH*MAXT];        // gx,gy,gw,gh (valid prefix)
__device__ int      g_gtcnt[NBATCH];
__device__ double   g_acc;

__device__ __forceinline__ float sigf(float x) { return 1.f / (1.f + expf(-x)); }

__device__ __forceinline__ float clipf(float x) { return fminf(fmaxf(x, EPSF), 1.0f); }

__device__ __forceinline__ float bcef(float p, float t) {
    return -(t * logf(clipf(p)) + (1.f - t) * logf(clipf(1.f - p)));
}

__device__ __forceinline__ float iou_cxcywh(float x1,float y1,float w1,float h1,
                                            float x2,float y2,float w2,float h2) {
    float cw = fminf(x1 + 0.5f*w1, x2 + 0.5f*w2) - fmaxf(x1 - 0.5f*w1, x2 - 0.5f*w2);
    float ch = fminf(y1 + 0.5f*h1, y2 + 0.5f*h2) - fmaxf(y1 - 0.5f*h1, y2 - 0.5f*h2);
    float inter = (cw > 0.f && ch > 0.f) ? cw*ch : 0.f;
    return inter / (w1*h1 + w2*h2 - inter);
}

// ============ Kernel 1: per-target assignment ============
__global__ void k_targets(const float* __restrict__ out,
                          const float* __restrict__ tgt,
                          const float* __restrict__ anch) {
    int b = blockIdx.x;
    int t = threadIdx.x;
    __shared__ int           s_flat[MAXT];
    __shared__ int           s_cls[MAXT];
    __shared__ unsigned char s_pos[MAXT];

    float tb[12];
    if (t < MAXT) {
        const float* p = tgt + (b*MAXT + t)*NLV;
        #pragma unroll
        for (int k = 0; k < 12; k++) tb[k] = p[k];
        s_pos[t] = (tb[1] > 0.f) ? 1 : 0;
    }
    __syncthreads();

    int flat = -1;
    if (t < MAXT) {
        bool valid = true;
        for (int k = 0; k <= t; k++) valid = valid && (s_pos[k] != 0);
        if (valid) {
            float gx = tb[1]*NWW, gy = tb[2]*NHH;
            float gw = tb[10]*NETWH, gh = tb[11]*NETWH;
            // best anchor (first max wins, like jnp.argmax)
            int best = 0; float bestr = -1.f;
            #pragma unroll
            for (int a = 0; a < NANC; a++) {
                float aw = anch[2*a], ah = anch[2*a+1];
                float inter = fminf(gw, aw) * fminf(gh, ah);
                float r = inter / (gw*gh + aw*ah - inter);
                if (r > bestr) { bestr = r; best = a; }
            }
            int gi = min(max((int)floorf(gx), 0), NWW-1);
            int gj = min(max((int)floorf(gy), 0), NHH-1);
            flat = best*NPIX + gj*NWW + gi;   // cell index within this batch
            // gather pred box at assigned cell
            int base = ((b*NANC + best)*NCH)*NPIX + gj*NWW + gi;
            float o0  = out[base];
            float o1  = out[base + NPIX];
            float o9  = out[base + 9*NPIX];
            float o10 = out[base + 10*NPIX];
            float aw = anch[2*best], ah = anch[2*best+1];
            float px = sigf(o0) + (float)gi;
            float py = sigf(o1) + (float)gj;
            float pw = expf(o9)  * aw;
            float ph = expf(o10) * ah;
            float iou_t = iou_cxcywh(gx, gy, gw, gh, px, py, pw, ph);
            int r = b*MAXT + t;
            float* rv = g_rec[r];
            rv[0] = gx - (float)gi;  rv[1] = gy - (float)gj;
            rv[2] = tb[3]; rv[3] = tb[4]; rv[4] = tb[5];
            rv[5] = tb[6]; rv[6] = tb[7]; rv[7] = tb[8]; rv[8] = tb[9];
            rv[9]  = logf(gw / aw);
            rv[10] = logf(gh / ah);
            rv[11] = iou_t;
            g_gtb[r] = make_float4(gx, gy, gw, gh);
        }
        s_flat[t] = flat;
        s_cls[t]  = (int)tb[0];
    }
    __syncthreads();

    if (t < MAXT && flat >= 0) {
        // winner = last valid target mapping to this cell (XLA scatter-set order)
        bool winner = true;
        for (int t2 = t+1; t2 < MAXT; t2++) if (s_flat[t2] == flat) winner = false;
        if (winner) {
            unsigned mask = 0;
            for (int t2 = 0; t2 < MAXT; t2++)
                if (s_flat[t2] == flat) mask |= (1u << s_cls[t2]);
            g_clsmask[b*MAXT + t] = mask;
            g_recidx[b*NANCH + flat] = b*MAXT + t;
        }
    }
    if (t == 0) {
        int cnt = 0;
        while (cnt < MAXT && s_pos[cnt]) cnt++;
        g_gtcnt[b] = cnt;
    }
}

// ============ Kernel 2: dense per-cell loss ============
__global__ void k_dense(const float* __restrict__ out,
                        const float* __restrict__ anch) {
    __shared__ float4 s_gt[MAXT];   // (xlo, xhi, ylo) packing below
    __shared__ float  s_glohi[MAXT][5]; // xlo,xhi,ylo,yhi,area
    __shared__ double s_red[256];

    int b = blockIdx.y;
    int tid = threadIdx.x;
    int cnt = g_gtcnt[b];
    if (tid < cnt) {
        float4 g = g_gtb[b*MAXT + tid];
        s_gt[tid] = g;
        s_glohi[tid][0] = g.x - 0.5f*g.z;
        s_glohi[tid][1] = g.x + 0.5f*g.z;
        s_glohi[tid][2] = g.y - 0.5f*g.w;
        s_glohi[tid][3] = g.y + 0.5f*g.w;
        s_glohi[tid][4] = g.z * g.w;
    }
    __syncthreads();

    double local = 0.0;
    int cell = blockIdx.x * blockDim.x + tid;
    if (cell < NANCH) {
        int a   = cell / NPIX;
        int rem = cell - a*NPIX;
        int j   = rem / NWW;
        int i   = rem - j*NWW;
        int base = ((b*NANC + a)*NCH)*NPIX + rem;

        float o0  = out[base];
        float o1  = out[base + NPIX];
        float o9  = out[base + 9*NPIX];
        float o10 = out[base + 10*NPIX];
        float o11 = out[base + 11*NPIX];

        float aw = anch[2*a], ah = anch[2*a+1];
        float s0 = sigf(o0);
        float s1 = sigf(o1);
        float px = s0 + (float)i, py = s1 + (float)j;
        float pw = expf(o9)*aw,   ph = expf(o10)*ah;
        float pxlo = px - 0.5f*pw, pxhi = px + 0.5f*pw;
        float pylo = py - 0.5f*ph, pyhi = py + 0.5f*ph;
        float pa   = pw * ph;

        // division-free IoU > 0.5 test:  3*inter > pa + ga
        bool ignored = false;
        for (int k = 0; k < cnt; k++) {
            float cw = fminf(pxhi, s_glohi[k][1]) - fmaxf(pxlo, s_glohi[k][0]);
            float ch = fminf(pyhi, s_glohi[k][3]) - fmaxf(pylo, s_glohi[k][2]);
            float inter = fmaxf(cw, 0.f) * fmaxf(ch, 0.f);
            if (3.f*inter > pa + s_glohi[k][4]) ignored = true;
        }

        float conf = sigf(o11);
        int rec = g_recidx[b*NANCH + cell];
        if (rec >= 0) {
            const float* rv = g_rec[rec];
            // conf (obj cell, mask=1)
            local += bcef(conf, rv[11]);
            // coord: bce on sigmoided x,y + L2 on raw w,h
            local += bcef(s0, rv[0]) + bcef(s1, rv[1]);
            float d9 = o9 - rv[9], d10 = o10 - rv[10];
            local += d9*d9 + d10*d10;
            // translation smooth-L1-like (rows 2..4)
            float o2 = out[base + 2*NPIX], o3 = out[base + 3*NPIX], o4 = out[base + 4*NPIX];
            float d2 = o2 - rv[2], d3 = o3 - rv[3], d4 = o4 - rv[4];
            float ss = d2*d2 + d3*d3 + d4*d4;
            float dis = sqrtf(ss);
            if (dis <= BETA_C) local += 0.5f*ss/BETA_C;
            else               local += fabsf(d2)+fabsf(d3)+fabsf(d4) - 0.5f*BETA_C;
            // rotation (rows 5..8, normalized)
            float o5 = out[base + 5*NPIX], o6 = out[base + 6*NPIX];
            float o7 = out[base + 7*NPIX], o8 = out[base + 8*NPIX];
            float nrm = fmaxf(sqrtf(o5*o5 + o6*o6 + o7*o7 + o8*o8), 1e-12f);
            local += fabsf(o5/nrm - rv[5]) + fabsf(o6/nrm - rv[6])
                   + fabsf(o7/nrm - rv[7]) + fabsf(o8/nrm - rv[8]);
            // class bce-with-logits
            unsigned mask = g_clsmask[rec];
            for (int c = 0; c < NCLS; c++) {
                float x  = out[base + (NLV + c)*NPIX];
                float tt = ((mask >> c) & 1u) ? 1.f : 0.f;
                local += fmaxf(x, 0.f) - x*tt + log1pf(expf(-fabsf(x)));
            }
        } else if (!ignored) {
            // noobj cell: bce(conf, 0) = -log(1-conf)
            local += -logf(clipf(1.f - conf));
        }
        // else mask==0 -> bce(0,0)==0
    }

    s_red[tid] = local;
    __syncthreads();
    for (int s = 128; s > 0; s >>= 1) {
        if (tid < s) s_red[tid] += s_red[tid + s];
        __syncthreads();
    }
    if (tid == 0) atomicAdd(&g_acc, s_red[0]);
}

__global__ void k_fin(float* o) {
    o[0] = (float)(g_acc * (1.0 / (double)NBATCH));
}

extern "C" void kernel_launch(void* const* d_in, const int* in_sizes, int n_in,
                              void* d_out, int out_size) {
    // identify inputs by element count (robust to ordering)
    const float* out  = nullptr;
    const float* tgt  = nullptr;
    const float* anch = nullptr;
    for (int k = 0; k < n_in; k++) {
        if (in_sizes[k] == NBATCH*NANC*NCH*NPIX) out  = (const float*)d_in[k];
        else if (in_sizes[k] == NBATCH*MAXT*NLV) tgt  = (const float*)d_in[k];
        else if (in_sizes[k] == NANC*2)          anch = (const float*)d_in[k];
    }

    static int*    recidx_ptr = nullptr;
    static double* acc_ptr    = nullptr;
    if (!recidx_ptr) {
        cudaGetSymbolAddress((void**)&recidx_ptr, g_recidx);
        cudaGetSymbolAddress((void**)&acc_ptr,    g_acc);
    }
    cudaMemsetAsync(recidx_ptr, 0xFF, sizeof(int)*CADT, 0);
    cudaMemsetAsync(acc_ptr,    0,    sizeof(double),   0);

    k_targets<<<NBATCH, 64>>>(out, tgt, anch);
    k_dense<<<dim3((NANCH + 255)/256, NBATCH), 256>>>(out, anch);
    k_fin<<<1, 1>>>((float*)d_out);
}

// round 3
// speedup vs baseline: 1.6815x; 1.6815x over previous
#include <cuda_runtime.h>
#include <math.h>

#define NBATCH 64
#define NANC   3
#define NCLS   13
#define NHH    76
#define NWW    76
#define NPIX   (NHH*NWW)          // 5776
#define NANCH  (NANC*NPIX)        // 17328
#define MAXT   50
#define NLV    12
#define NCH    (NLV+NCLS)         // 25
#define BETA_C 0.028f
#define NETWH  608.0f

#define GRPB   (NANCH/4)          // 4332 groups of 4 cells per batch
#define DBLKX  17                 // ceil(4332/256)
#define NBLKS  (DBLKX*NBATCH)     // 1088 dense blocks

// -------- persistent scratch (device globals; zero-initialized) --------
__device__ float4   g_gtlh[NBATCH*MAXT];   // xlo,xhi,ylo,yhi per GT
__device__ float    g_ga[NBATCH*MAXT];     // GT areas
__device__ float    g_gamin[NBATCH];
__device__ int      g_gtcnt[NBATCH];
__device__ double   g_acc;                 // reset by finalizer each launch
__device__ unsigned g_done;                // reset by finalizer each launch

__device__ __forceinline__ float softplusf(float x) {
    return fmaxf(x, 0.f) + __logf(1.f + __expf(-fabsf(x)));
}
// -(t*log(sig(x)) + (1-t)*log(1-sig(x))) == softplus(x) - t*x
__device__ __forceinline__ float bce_logit(float x, float t) {
    return softplusf(x) - t * x;
}
__device__ __forceinline__ float sigfast(float x) {
    return 1.f / (1.f + __expf(-x));
}

// exact reference-style ignore test for one cell (shared by both kernels)
__device__ __forceinline__ bool cell_ignored(
    float o0, float o1, float o9, float o10, float aw, float ah,
    int i, int j, int cnt, const float4* lh, const float* ga)
{
    float pw = __expf(o9) * aw, ph = __expf(o10) * ah;
    float px = sigfast(o0) + (float)i;
    float py = sigfast(o1) + (float)j;
    float pxlo = px - 0.5f*pw, pxhi = px + 0.5f*pw;
    float pylo = py - 0.5f*ph, pyhi = py + 0.5f*ph;
    float pa = pw * ph;
    bool ig = false;
    for (int k = 0; k < cnt; k++) {
        float cw = fminf(pxhi, lh[k].y) - fmaxf(pxlo, lh[k].x);
        float ch = fminf(pyhi, lh[k].w) - fmaxf(pylo, lh[k].z);
        float inter = fmaxf(cw, 0.f) * fmaxf(ch, 0.f);
        if (3.f*inter > pa + ga[k]) ig = true;   // iou > 0.5
    }
    return ig;
}

__device__ __forceinline__ float iou_div(float x1,float y1,float w1,float h1,
                                         float x2,float y2,float w2,float h2) {
    float cw = fminf(x1+0.5f*w1, x2+0.5f*w2) - fmaxf(x1-0.5f*w1, x2-0.5f*w2);
    float ch = fminf(y1+0.5f*h1, y2+0.5f*h2) - fmaxf(y1-0.5f*h1, y2-0.5f*h2);
    float inter = (cw > 0.f && ch > 0.f) ? cw*ch : 0.f;
    return inter / (w1*h1 + w2*h2 - inter);
}

// ============ Kernel 1: targets + obj-cell losses ============
__global__ void k_targets(const float* __restrict__ out,
                          const float* __restrict__ tgt,
                          const float* __restrict__ anch) {
    int b = blockIdx.x;
    int t = threadIdx.x;
    __shared__ float    st[MAXT*12];
    __shared__ int      s_flat[MAXT];
    __shared__ int      s_cls[MAXT];
    __shared__ float    s_ga[MAXT];
    __shared__ float4   s_lh[MAXT];
    __shared__ float    s_gamin;
    __shared__ unsigned s_m0, s_m1;
    __shared__ double   s_part[2];

    // coalesced stage of targets
    for (int i = t; i < MAXT*12; i += 64) st[i] = tgt[b*MAXT*12 + i];
    __syncthreads();

    bool pos = (t < MAXT) && (st[t*12 + 1] > 0.f);
    unsigned bal = __ballot_sync(0xFFFFFFFFu, pos);
    if ((t & 31) == 0) { if (t < 32) s_m0 = bal; else s_m1 = bal; }
    __syncthreads();
    int cnt;
    if (~s_m0) cnt = __ffs(~s_m0) - 1;
    else       cnt = 32 + __ffs(~s_m1) - 1;
    if (cnt > MAXT) cnt = MAXT;

    float gx=0, gy=0, gw=0, gh=0, aw=0, ah=0;
    int best=0, gi=0, gj=0, flat=-1;
    if (t < cnt) {
        const float* tb = st + t*12;
        gx = tb[1]*(float)NWW;  gy = tb[2]*(float)NHH;
        gw = tb[10]*NETWH;      gh = tb[11]*NETWH;
        float bestr = -1.f;
        #pragma unroll
        for (int a = 0; a < NANC; a++) {
            float aw_ = anch[2*a], ah_ = anch[2*a+1];
            float inter = fminf(gw, aw_) * fminf(gh, ah_);
            float r = inter / (gw*gh + aw_*ah_ - inter);
            if (r > bestr) { bestr = r; best = a; }
        }
        gi = min(max((int)floorf(gx), 0), NWW-1);
        gj = min(max((int)floorf(gy), 0), NHH-1);
        flat = best*NPIX + gj*NWW + gi;
        aw = anch[2*best]; ah = anch[2*best+1];
        s_ga[t] = gw*gh;
        s_lh[t] = make_float4(gx-0.5f*gw, gx+0.5f*gw, gy-0.5f*gh, gy+0.5f*gh);
    }
    if (t < MAXT) { s_flat[t] = flat; s_cls[t] = (int)st[t*12]; }
    if (t == 0) {
        g_gtcnt[b] = cnt;
    }
    __syncthreads();

    // export GT info for dense kernel + gamin
    if (t < cnt) { g_gtlh[b*MAXT + t] = s_lh[t]; g_ga[b*MAXT + t] = s_ga[t]; }
    if (t == 0) {
        float gm = 1e30f;
        for (int k = 0; k < cnt; k++) gm = fminf(gm, s_ga[k]);
        g_gamin[b] = gm;
        s_gamin = gm;
    }
    __syncthreads();

    double local = 0.0;
    if (t < cnt) {
        bool winner = true; unsigned mask = 0;
        for (int t2 = 0; t2 < cnt; t2++) {
            if (s_flat[t2] == flat) {
                if (t2 > t) winner = false;
                mask |= 1u << s_cls[t2];
            }
        }
        if (winner) {
            const float* tb = st + t*12;
            const float* basep = out + (size_t)(b*NANC + best)*NCH*NPIX + (gj*NWW + gi);
            float o[12];
            #pragma unroll
            for (int c = 0; c < 12; c++) o[c] = basep[c*NPIX];

            float l = 0.f;
            // coord: bce on x,y + L2 on w,h
            float tx = gx - (float)gi, ty = gy - (float)gj;
            l += bce_logit(o[0], tx) + bce_logit(o[1], ty);
            float r9 = logf(gw/aw), r10 = logf(gh/ah);
            float d9 = o[9]-r9, d10 = o[10]-r10;
            l += d9*d9 + d10*d10;
            // translation smooth-L1
            float d2 = o[2]-tb[3], d3 = o[3]-tb[4], d4 = o[4]-tb[5];
            float ss = d2*d2 + d3*d3 + d4*d4;
            float dis = sqrtf(ss);
            if (dis <= BETA_C) l += 0.5f*ss/BETA_C;
            else               l += fabsf(d2)+fabsf(d3)+fabsf(d4) - 0.5f*BETA_C;
            // rotation (normalized 4-vec)
            float nrm = fmaxf(sqrtf(o[5]*o[5]+o[6]*o[6]+o[7]*o[7]+o[8]*o[8]), 1e-12f);
            l += fabsf(o[5]/nrm - tb[6]) + fabsf(o[6]/nrm - tb[7])
               + fabsf(o[7]/nrm - tb[8]) + fabsf(o[8]/nrm - tb[9]);
            // conf vs iou_t
            float px = sigfast(o[0]) + (float)gi;
            float py = sigfast(o[1]) + (float)gj;
            float pw = __expf(o[9])*aw, ph = __expf(o[10])*ah;
            float iou_t = iou_div(gx, gy, gw, gh, px, py, pw, ph);
            l += bce_logit(o[11], iou_t);
            // class bce-with-logits
            #pragma unroll
            for (int c = 0; c < NCLS; c++) {
                float x  = basep[(NLV + c)*NPIX];
                float tt = ((mask >> c) & 1u) ? 1.f : 0.f;
                l += bce_logit(x, tt);
            }
            // subtract the dense kernel's noobj double-count (same code path)
            float pa_gate = aw*ah*__expf(o[9]+o[10]);
            bool ig = false;
            if (2.f*pa_gate > 0.99f*s_gamin)
                ig = cell_ignored(o[0], o[1], o[9], o[10], aw, ah, gi, gj,
                                  cnt, s_lh, s_ga);
            if (!ig) l -= softplusf(o[11]);
            local = (double)l;
        }
    }

    // block reduce (2 warps)
    #pragma unroll
    for (int off = 16; off > 0; off >>= 1)
        local += __shfl_down_sync(0xFFFFFFFFu, local, off);
    if ((t & 31) == 0) s_part[t >> 5] = local;
    __syncthreads();
    if (t == 0) atomicAdd(&g_acc, s_part[0] + s_part[1]);
}

// ============ Kernel 2: dense noobj loss (3 channels, pruned) ============
__global__ void __launch_bounds__(256) k_dense(const float* __restrict__ out,
                                               const float* __restrict__ anch,
                                               float* __restrict__ d_out) {
    __shared__ float4 s_lh[MAXT];
    __shared__ float  s_ga[MAXT];
    __shared__ int    s_cnt;
    __shared__ float  s_gm;
    __shared__ double s_wsum[8];

    int b   = blockIdx.y;
    int tid = threadIdx.x;
    if (tid == 0) { s_cnt = g_gtcnt[b]; s_gm = g_gamin[b]; }
    __syncthreads();
    int cnt = s_cnt;
    if (tid < cnt) { s_lh[tid] = g_gtlh[b*MAXT + tid]; s_ga[tid] = g_ga[b*MAXT + tid]; }
    __syncthreads();

    float local = 0.f;
    int grp = blockIdx.x * 256 + tid;
    if (grp < GRPB) {
        int cell0 = grp * 4;
        int a = (cell0 >= 2*NPIX) ? 2 : (cell0 >= NPIX ? 1 : 0);
        int rem = cell0 - a*NPIX;
        const float* basep = out + (size_t)(b*NANC + a)*NCH*NPIX + rem;
        float aw = anch[2*a], ah = anch[2*a+1];
        float awah = aw*ah;
        float gm = s_gm;

        float4 v9  = *reinterpret_cast<const float4*>(basep + 9*NPIX);
        float4 v10 = *reinterpret_cast<const float4*>(basep + 10*NPIX);
        float4 v11 = *reinterpret_cast<const float4*>(basep + 11*NPIX);
        float a9[4]  = {v9.x,  v9.y,  v9.z,  v9.w};
        float a10[4] = {v10.x, v10.y, v10.z, v10.w};
        float a11[4] = {v11.x, v11.y, v11.z, v11.w};

        #pragma unroll
        for (int s = 0; s < 4; s++) {
            float o9 = a9[s], o10 = a10[s], o11 = a11[s];
            float pa_gate = awah * __expf(o9 + o10);
            bool ig = false;
            if (2.f*pa_gate > 0.99f*gm) {
                float o0 = basep[s];
                float o1 = basep[NPIX + s];
                int cell = rem + s;
                int j = cell / NWW;
                int i = cell - j*NWW;
                ig = cell_ignored(o0, o1, o9, o10, aw, ah, i, j, cnt, s_lh, s_ga);
            }
            if (!ig) local += softplusf(o11);
        }
    }

    // block reduce in double
    double v = (double)local;
    #pragma unroll
    for (int off = 16; off > 0; off >>= 1)
        v += __shfl_down_sync(0xFFFFFFFFu, v, off);
    int lane = tid & 31, wid = tid >> 5;
    if (lane == 0) s_wsum[wid] = v;
    __syncthreads();
    if (tid == 0) {
        double blocksum = 0.0;
        #pragma unroll
        for (int w = 0; w < 8; w++) blocksum += s_wsum[w];
        atomicAdd(&g_acc, blocksum);
        __threadfence();
        unsigned old = atomicAdd(&g_done, 1u);
        if (old == NBLKS - 1) {
            double tot = atomicAdd(&g_acc, 0.0);   // ordered read
            d_out[0] = (float)(tot * (1.0/(double)NBATCH));
            g_acc  = 0.0;        // self-reset for next (identical) launch
            __threadfence();
            g_done = 0u;
        }
    }
}

extern "C" void kernel_launch(void* const* d_in, const int* in_sizes, int n_in,
                              void* d_out, int out_size) {
    const float* out  = nullptr;
    const float* tgt  = nullptr;
    const float* anch = nullptr;
    for (int k = 0; k < n_in; k++) {
        if      (in_sizes[k] == NBATCH*NANC*NCH*NPIX) out  = (const float*)d_in[k];
        else if (in_sizes[k] == NBATCH*MAXT*NLV)      tgt  = (const float*)d_in[k];
        else if (in_sizes[k] == NANC*2)               anch = (const float*)d_in[k];
    }
    k_targets<<<NBATCH, 64>>>(out, tgt, anch);
    k_dense<<<dim3(DBLKX, NBATCH), 256>>>(out, anch, (float*)d_out);
}

// round 4
// speedup vs baseline: 3.8675x; 2.3000x over previous
#include <cuda_runtime.h>
#include <math.h>

#define NBATCH 64
#define NANC   3
#define NCLS   13
#define NHH    76
#define NWW    76
#define NPIX   (NHH*NWW)          // 5776
#define NANCH  (NANC*NPIX)        // 17328
#define MAXT   50
#define NLV    12
#define NCH    (NLV+NCLS)         // 25
#define BETA_C 0.028f
#define NETWH  608.0f

#define GPB_TOT (NANCH/4)         // 4332 groups (of 4 cells) per batch
#define DBPB    4                 // dense blocks per batch
#define GPBLK   (GPB_TOT/DBPB)    // 1083 groups per dense block
#define DBLKS   (NBATCH*DBPB)     // 256 dense blocks
#define NBLKS   (DBLKS+NBATCH)    // 320 total blocks

// -------- persistent scratch (zero-initialized; self-resetting) --------
__device__ double   g_acc;
__device__ unsigned g_done;

__device__ __forceinline__ float softplusf(float x) {
    return fmaxf(x, 0.f) + __logf(1.f + __expf(-fabsf(x)));
}
__device__ __forceinline__ float bce_logit(float x, float t) {
    return softplusf(x) - t * x;      // == bce(sigmoid(x), t)
}
__device__ __forceinline__ float sigfast(float x) {
    return 1.f / (1.f + __expf(-x));
}

__device__ __forceinline__ bool cell_ignored(
    float o0, float o1, float o9, float o10, float aw, float ah,
    int i, int j, int cnt, const float4* lh, const float* ga)
{
    float pw = __expf(o9) * aw, ph = __expf(o10) * ah;
    float px = sigfast(o0) + (float)i;
    float py = sigfast(o1) + (float)j;
    float pxlo = px - 0.5f*pw, pxhi = px + 0.5f*pw;
    float pylo = py - 0.5f*ph, pyhi = py + 0.5f*ph;
    float pa = pw * ph;
    bool ig = false;
    for (int k = 0; k < cnt; k++) {
        float cw = fminf(pxhi, lh[k].y) - fmaxf(pxlo, lh[k].x);
        float ch = fminf(pyhi, lh[k].w) - fmaxf(pylo, lh[k].z);
        float inter = fmaxf(cw, 0.f) * fmaxf(ch, 0.f);
        if (3.f*inter > pa + ga[k]) ig = true;     // iou > 0.5
    }
    return ig;
}

__device__ __forceinline__ float iou_div(float x1,float y1,float w1,float h1,
                                         float x2,float y2,float w2,float h2) {
    float cw = fminf(x1+0.5f*w1, x2+0.5f*w2) - fmaxf(x1-0.5f*w1, x2-0.5f*w2);
    float ch = fminf(y1+0.5f*h1, y2+0.5f*h2) - fmaxf(y1-0.5f*h1, y2-0.5f*h2);
    float inter = (cw > 0.f && ch > 0.f) ? cw*ch : 0.f;
    return inter / (w1*h1 + w2*h2 - inter);
}

__global__ void __launch_bounds__(256)
k_fused(const float* __restrict__ out,
        const float* __restrict__ tgt,
        const float* __restrict__ anch,
        float* __restrict__ d_out)
{
    __shared__ float    st[MAXT*12];
    __shared__ float4   s_lh[MAXT];
    __shared__ float    s_ga[MAXT];
    __shared__ int      s_flat[MAXT];
    __shared__ int      s_cls[MAXT];
    __shared__ float    s_anc[6];
    __shared__ float    s_gm;
    __shared__ int      s_cnt;
    __shared__ unsigned s_m0, s_m1;
    __shared__ double   s_wsum[8];

    int tid = threadIdx.x;
    if (tid < 6) s_anc[tid] = anch[tid];
    double local = 0.0;

    if (blockIdx.x < DBLKS) {
        // ================= dense role: noobj loss over 1083 groups =================
        int b    = blockIdx.x >> 2;
        int base = (blockIdx.x & 3) * GPBLK;

        bool pos = false;
        if (tid < MAXT) {
            const float* p = tgt + b*MAXT*12 + tid*12;
            float x = p[1], y = p[2];
            float gw = p[10]*NETWH, gh = p[11]*NETWH;
            float gx = x*(float)NWW, gy = y*(float)NHH;
            s_lh[tid] = make_float4(gx-0.5f*gw, gx+0.5f*gw, gy-0.5f*gh, gy+0.5f*gh);
            s_ga[tid] = gw*gh;
            pos = (x > 0.f);
        }
        if (tid < 64) {
            unsigned bal = __ballot_sync(0xFFFFFFFFu, pos);
            if ((tid & 31) == 0) { if (tid < 32) s_m0 = bal; else s_m1 = bal; }
        }
        __syncthreads();
        if (tid == 0) {
            int c = (~s_m0) ? (__ffs(~s_m0) - 1) : (32 + __ffs(~s_m1) - 1);
            if (c > MAXT) c = MAXT;
            float gm = 1e30f;
            for (int k = 0; k < c; k++) gm = fminf(gm, s_ga[k]);
            s_cnt = c; s_gm = gm;
        }
        __syncthreads();
        int   cnt = s_cnt;
        float gm  = s_gm;

        float lf = 0.f;
        #pragma unroll
        for (int k = 0; k < 5; k++) {
            int rg = tid + k*256;
            if (rg < GPBLK) {
                int g = base + rg;
                int cell0 = g * 4;
                int a = (cell0 >= 2*NPIX) ? 2 : (cell0 >= NPIX ? 1 : 0);
                int rem = cell0 - a*NPIX;
                const float* basep = out + (size_t)(b*NANC + a)*NCH*NPIX + rem;
                float aw = s_anc[2*a], ah = s_anc[2*a+1];
                float awah = aw*ah;

                float4 v9  = *reinterpret_cast<const float4*>(basep + 9*NPIX);
                float4 v10 = *reinterpret_cast<const float4*>(basep + 10*NPIX);
                float4 v11 = *reinterpret_cast<const float4*>(basep + 11*NPIX);
                float a9[4]  = {v9.x,  v9.y,  v9.z,  v9.w};
                float a10[4] = {v10.x, v10.y, v10.z, v10.w};
                float a11[4] = {v11.x, v11.y, v11.z, v11.w};

                #pragma unroll
                for (int s = 0; s < 4; s++) {
                    float o9 = a9[s], o10 = a10[s], o11 = a11[s];
                    float pa_gate = awah * __expf(o9 + o10);
                    bool ig = false;
                    if (2.f*pa_gate > 0.99f*gm) {
                        float o0 = basep[s];
                        float o1 = basep[NPIX + s];
                        int cell = rem + s;
                        int j = cell / NWW;
                        int i = cell - j*NWW;
                        ig = cell_ignored(o0, o1, o9, o10, aw, ah, i, j,
                                          cnt, s_lh, s_ga);
                    }
                    if (!ig) lf += softplusf(o11);
                }
            }
        }
        local = (double)lf;
    } else {
        // ================= target role: obj-cell losses for one batch =================
        int b = blockIdx.x - DBLKS;
        for (int i = tid; i < MAXT*12; i += 256) st[i] = tgt[b*MAXT*12 + i];
        __syncthreads();

        int t = tid;
        bool pos = (t < MAXT) && (st[t*12 + 1] > 0.f);
        if (t < 64) {
            unsigned bal = __ballot_sync(0xFFFFFFFFu, pos);
            if ((t & 31) == 0) { if (t < 32) s_m0 = bal; else s_m1 = bal; }
        }
        __syncthreads();
        if (t == 0) {
            int c = (~s_m0) ? (__ffs(~s_m0) - 1) : (32 + __ffs(~s_m1) - 1);
            if (c > MAXT) c = MAXT;
            s_cnt = c;
        }
        __syncthreads();
        int cnt = s_cnt;

        float gx=0, gy=0, gw=0, gh=0, aw=0, ah=0;
        int best=0, gi=0, gj=0, flat=-1;
        if (t < MAXT) {
            const float* tb = st + t*12;
            gx = tb[1]*(float)NWW;  gy = tb[2]*(float)NHH;
            gw = tb[10]*NETWH;      gh = tb[11]*NETWH;
            s_ga[t] = gw*gh;
            s_lh[t] = make_float4(gx-0.5f*gw, gx+0.5f*gw, gy-0.5f*gh, gy+0.5f*gh);
            if (t < cnt) {
                float bestr = -1.f;
                #pragma unroll
                for (int a = 0; a < NANC; a++) {
                    float aw_ = s_anc[2*a], ah_ = s_anc[2*a+1];
                    float inter = fminf(gw, aw_) * fminf(gh, ah_);
                    float r = inter / (gw*gh + aw_*ah_ - inter);
                    if (r > bestr) { bestr = r; best = a; }
                }
                gi = min(max((int)floorf(gx), 0), NWW-1);
                gj = min(max((int)floorf(gy), 0), NHH-1);
                flat = best*NPIX + gj*NWW + gi;
                aw = s_anc[2*best]; ah = s_anc[2*best+1];
            }
            s_flat[t] = flat;
            s_cls[t]  = (int)tb[0];
        }
        __syncthreads();
        if (t == 0) {
            float gm = 1e30f;
            for (int k = 0; k < cnt; k++) gm = fminf(gm, s_ga[k]);
            s_gm = gm;
        }
        __syncthreads();

        if (t < cnt) {
            bool winner = true; unsigned mask = 0;
            for (int t2 = 0; t2 < cnt; t2++) {
                if (s_flat[t2] == flat) {
                    if (t2 > t) winner = false;
                    mask |= 1u << s_cls[t2];
                }
            }
            if (winner) {
                const float* tb = st + t*12;
                const float* basep = out + (size_t)(b*NANC + best)*NCH*NPIX
                                         + (gj*NWW + gi);
                float o[12];
                #pragma unroll
                for (int c = 0; c < 12; c++) o[c] = basep[c*NPIX];
                float cl[NCLS];
                #pragma unroll
                for (int c = 0; c < NCLS; c++) cl[c] = basep[(NLV + c)*NPIX];

                float l = 0.f;
                float tx = gx - (float)gi, ty = gy - (float)gj;
                l += bce_logit(o[0], tx) + bce_logit(o[1], ty);
                float r9 = logf(gw/aw), r10 = logf(gh/ah);
                float d9 = o[9]-r9, d10 = o[10]-r10;
                l += d9*d9 + d10*d10;
                float d2 = o[2]-tb[3], d3 = o[3]-tb[4], d4 = o[4]-tb[5];
                float ss = d2*d2 + d3*d3 + d4*d4;
                float dis = sqrtf(ss);
                if (dis <= BETA_C) l += 0.5f*ss/BETA_C;
                else               l += fabsf(d2)+fabsf(d3)+fabsf(d4) - 0.5f*BETA_C;
                float nrm = fmaxf(sqrtf(o[5]*o[5]+o[6]*o[6]+o[7]*o[7]+o[8]*o[8]), 1e-12f);
                l += fabsf(o[5]/nrm - tb[6]) + fabsf(o[6]/nrm - tb[7])
                   + fabsf(o[7]/nrm - tb[8]) + fabsf(o[8]/nrm - tb[9]);
                float px = sigfast(o[0]) + (float)gi;
                float py = sigfast(o[1]) + (float)gj;
                float pw = __expf(o[9])*aw, ph = __expf(o[10])*ah;
                float iou_t = iou_div(gx, gy, gw, gh, px, py, pw, ph);
                l += bce_logit(o[11], iou_t);
                #pragma unroll
                for (int c = 0; c < NCLS; c++) {
                    float tt = ((mask >> c) & 1u) ? 1.f : 0.f;
                    l += bce_logit(cl[c], tt);
                }
                // subtract the dense role's noobj contribution for this cell
                float pa_gate = aw*ah*__expf(o[9]+o[10]);
                bool ig = false;
                if (2.f*pa_gate > 0.99f*s_gm)
                    ig = cell_ignored(o[0], o[1], o[9], o[10], aw, ah, gi, gj,
                                      cnt, s_lh, s_ga);
                if (!ig) l -= softplusf(o[11]);
                local = (double)l;
            }
        }
    }

    // ================= common block reduction + last-block finalize =================
    #pragma unroll
    for (int off = 16; off > 0; off >>= 1)
        local += __shfl_down_sync(0xFFFFFFFFu, local, off);
    int lane = tid & 31, wid = tid >> 5;
    if (lane == 0) s_wsum[wid] = local;
    __syncthreads();
    if (tid == 0) {
        double bs = 0.0;
        #pragma unroll
        for (int w = 0; w < 8; w++) bs += s_wsum[w];
        atomicAdd(&g_acc, bs);
        __threadfence();
        unsigned old = atomicAdd(&g_done, 1u);
        if (old == NBLKS - 1) {
            double tot = atomicAdd(&g_acc, 0.0);   // ordered read
            d_out[0] = (float)(tot * (1.0/(double)NBATCH));
            g_acc = 0.0;                           // self-reset for graph replay
            __threadfence();
            g_done = 0u;
        }
    }
}

extern "C" void kernel_launch(void* const* d_in, const int* in_sizes, int n_in,
                              void* d_out, int out_size) {
    const float* out  = nullptr;
    const float* tgt  = nullptr;
    const float* anch = nullptr;
    for (int k = 0; k < n_in; k++) {
        if      (in_sizes[k] == NBATCH*NANC*NCH*NPIX) out  = (const float*)d_in[k];
        else if (in_sizes[k] == NBATCH*MAXT*NLV)      tgt  = (const float*)d_in[k];
        else if (in_sizes[k] == NANC*2)               anch = (const float*)d_in[k];
    }
    k_fused<<<NBLKS, 256>>>(out, tgt, anch, (float*)d_out);
}